// round 6
// baseline (speedup 1.0000x reference)
#include <cuda_runtime.h>
#include <cuda_bf16.h>
#include <cstdint>

#define NFIELD 39
#define VOCAB  200000
#define BATCH  16384
#define ROWSPB 128
#define THREADS 512
#define NCHUNK 10          // 10 chunks x 4 ksteps x 16k = 640 padded k

// B fragments, m16n8k16 per-lane layout:
// [hl(2)][kstep(40)][ntile(8)][lane(32)][reg(2)] uint32 (bf16x2) = 160KB
__device__ __align__(16) uint32_t BfragG[2 * 40 * 8 * 32 * 2];

__global__ void prep_kernel(const float* __restrict__ W1, const float* __restrict__ Wi) {
    int i = blockIdx.x * blockDim.x + threadIdx.x;
    if (i >= 2 * 40 * 8 * 32 * 2) return;
    int reg = i & 1;
    int l   = (i >> 1) & 31;
    int t   = (i >> 6) & 7;
    int s   = (i >> 9) % 40;
    int hl  = (i >> 9) / 40;
    int n  = t * 8 + (l >> 2);
    int k0 = s * 16 + (l & 3) * 2 + reg * 8;
    float v0 = 0.f, v1 = 0.f;
    if (k0 < 624)     v0 = (n < 32) ? W1[n * 624 + k0]     : Wi[(n - 32) * 624 + k0];
    if (k0 + 1 < 624) v1 = (n < 32) ? W1[n * 624 + k0 + 1] : Wi[(n - 32) * 624 + k0 + 1];
    float h0 = __bfloat162float(__float2bfloat16(v0));
    float h1 = __bfloat162float(__float2bfloat16(v1));
    uint32_t word;
    if (hl == 0) {
        asm("cvt.rn.bf16x2.f32 %0, %1, %2;" : "=r"(word) : "f"(h1), "f"(h0));
    } else {
        float r0 = v0 - h0, r1 = v1 - h1;
        asm("cvt.rn.bf16x2.f32 %0, %1, %2;" : "=r"(word) : "f"(r1), "f"(r0));
    }
    BfragG[i] = word;
}

__device__ __forceinline__ uint32_t packbf(float lo_elem, float hi_elem) {
    uint32_t r;
    asm("cvt.rn.bf16x2.f32 %0, %1, %2;" : "=r"(r) : "f"(hi_elem), "f"(lo_elem));
    return r;
}

__device__ __forceinline__ void mma16816(float* d, uint32_t a0, uint32_t a1, uint32_t a2, uint32_t a3,
                                         uint32_t b0, uint32_t b1) {
    asm volatile("mma.sync.aligned.m16n8k16.row.col.f32.bf16.bf16.f32 "
                 "{%0,%1,%2,%3}, {%4,%5,%6,%7}, {%8,%9}, {%0,%1,%2,%3};"
                 : "+f"(d[0]), "+f"(d[1]), "+f"(d[2]), "+f"(d[3])
                 : "r"(a0), "r"(a1), "r"(a2), "r"(a3), "r"(b0), "r"(b1));
}

// smem layout (bytes):
//   A frags: 2 bufs x [hl2][slab8][ks4][lane32][16B] = 2 x 32768 @ 0
//   B frags: [hl2][gs40][t8][lane32][8B] = 163840 @ 65536
#define OFF_A 0
#define ABUF  32768
#define OFF_B 65536
#define SMEM_BYTES (65536 + 163840)
// epilogue aliases inside the A region (65536 B):
#define EXP_FO 0        // 128 x 33 floats  (first_order)
#define EXP_S  16896    // 128 x 33 floats  (s)
#define EXP_M  33792    // 2145 floats      (MLP weights)
#define EXP_H  42384    // 128 x 33 floats  (h1)

__global__ __launch_bounds__(THREADS, 1)
void pnn_kernel(const int*   __restrict__ Xi,
                const float* __restrict__ Xv,
                const float* __restrict__ tables,
                const float* __restrict__ lin1_w,
                const float* __restrict__ lin1_b,
                const float* __restrict__ lin2_w,
                const float* __restrict__ lin2_b,
                const float* __restrict__ last_w,
                const float* __restrict__ last_b,
                float*       __restrict__ out) {
    extern __shared__ unsigned char smem[];

    const int tid = threadIdx.x;
    const int wid = tid >> 5;
    const int l   = tid & 31;
    const int b0  = blockIdx.x * ROWSPB;

    // MMA mapping: warp -> (slab, n-half)
    const int slab = wid >> 1;       // 16-row slab 0..7
    const int nh   = wid & 1;        // ntiles [nh*4, nh*4+4)

    // gather mapping: 4 threads per row, 1 field per thread per chunk
    const int grow = tid >> 2;       // row 0..127
    const int q    = tid & 3;        // kstep-within-chunk this thread fills
    const int gslab = grow >> 4;
    const int gm    = grow & 15;
    const int glane4 = (gm & 7) * 4;
    const int gregoff = (gm >= 8) ? 8 : 0;

    // ---- stage B fragments (160KB, coalesced) ----
    {
        const uint4* src = (const uint4*)BfragG;
        uint4* dst = (uint4*)(smem + OFF_B);
        #pragma unroll 4
        for (int i = tid; i < 163840 / 16; i += THREADS) dst[i] = src[i];
    }

    // ---- preload all (idx, xv) for this thread's fields ----
    int   fidx[NCHUNK];
    float fxv[NCHUNK];
    #pragma unroll
    for (int c = 0; c < NCHUNK; ++c) {
        int f = c * 4 + q;
        if (f < NFIELD) {
            fidx[c] = Xi[(size_t)(b0 + grow) * NFIELD + f];
            fxv[c]  = Xv[(size_t)(b0 + grow) * NFIELD + f];
        } else {
            fidx[c] = 0;
            fxv[c]  = 0.f;   // xv=0 -> zero A frag
        }
    }

    float acc[4][4];
    #pragma unroll
    for (int t = 0; t < 4; ++t)
        #pragma unroll
        for (int r = 0; r < 4; ++r) acc[t][r] = 0.f;

    // ---- prologue: gather chunk 0 into buf 0 ----
    {
        const int f = q;   // chunk 0 field
        const float4* rp = (const float4*)tables + ((long)f * VOCAB + fidx[0]) * 4;
        float4 t0 = rp[0], t1 = rp[1], t2 = rp[2], t3 = rp[3];
        float xv = fxv[0];
        float v[16] = {t0.x * xv, t0.y * xv, t0.z * xv, t0.w * xv,
                       t1.x * xv, t1.y * xv, t1.z * xv, t1.w * xv,
                       t2.x * xv, t2.y * xv, t2.z * xv, t2.w * xv,
                       t3.x * xv, t3.y * xv, t3.z * xv, t3.w * xv};
        float hi[16], rs[16];
        #pragma unroll
        for (int e = 0; e < 16; ++e) {
            hi[e] = __bfloat162float(__float2bfloat16(v[e]));
            rs[e] = v[e] - hi[e];
        }
        unsigned char* ah = smem + OFF_A + (((0 * 8 + gslab) * 4 + q) * 32) * 16;
        unsigned char* al = smem + OFF_A + (((1 * 8 + gslab) * 4 + q) * 32) * 16;
        #pragma unroll
        for (int p = 0; p < 4; ++p) {
            *(uint2*)(ah + (glane4 + p) * 16 + gregoff) =
                make_uint2(packbf(v[2 * p], v[2 * p + 1]), packbf(v[8 + 2 * p], v[9 + 2 * p]));
            *(uint2*)(al + (glane4 + p) * 16 + gregoff) =
                make_uint2(packbf(rs[2 * p], rs[2 * p + 1]), packbf(rs[8 + 2 * p], rs[9 + 2 * p]));
        }
    }
    __syncthreads();

    // ---- pipelined main loop ----
    #pragma unroll 1
    for (int c = 0; c < NCHUNK; ++c) {
        const int bc = c & 1;

        // 1) issue next chunk's table LDGs (latency hidden behind MMA below)
        float4 n0 = {0,0,0,0}, n1 = {0,0,0,0}, n2 = {0,0,0,0}, n3 = {0,0,0,0};
        float nxv = 0.f;
        if (c + 1 < NCHUNK) {
            const int f = (c + 1) * 4 + q;
            nxv = fxv[c + 1];
            const float4* rp = (const float4*)tables + ((long)f * VOCAB + fidx[c + 1]) * 4;
            if (f < NFIELD) { n0 = rp[0]; n1 = rp[1]; n2 = rp[2]; n3 = rp[3]; }
        }

        // 2) MMA on chunk c
        #pragma unroll
        for (int s = 0; s < 4; ++s) {
            const int gs = c * 4 + s;
            uint4 Ah = *(const uint4*)(smem + OFF_A + bc * ABUF + (((0 * 8 + slab) * 4 + s) * 32 + l) * 16);
            uint4 Al = *(const uint4*)(smem + OFF_A + bc * ABUF + (((1 * 8 + slab) * 4 + s) * 32 + l) * 16);
            #pragma unroll
            for (int t4 = 0; t4 < 4; ++t4) {
                const int t = nh * 4 + t4;
                uint2 Bh = *(const uint2*)(smem + OFF_B + (((0 * 40 + gs) * 8 + t) * 32 + l) * 8);
                uint2 Bl = *(const uint2*)(smem + OFF_B + (((1 * 40 + gs) * 8 + t) * 32 + l) * 8);
                mma16816(acc[t4], Ah.x, Ah.z, Ah.y, Ah.w, Bh.x, Bh.y);
                mma16816(acc[t4], Ah.x, Ah.z, Ah.y, Ah.w, Bl.x, Bl.y);
                mma16816(acc[t4], Al.x, Al.z, Al.y, Al.w, Bh.x, Bh.y);
            }
        }

        // 3) convert + store chunk c+1 into the other buffer
        if (c + 1 < NCHUNK) {
            float v[16] = {n0.x * nxv, n0.y * nxv, n0.z * nxv, n0.w * nxv,
                           n1.x * nxv, n1.y * nxv, n1.z * nxv, n1.w * nxv,
                           n2.x * nxv, n2.y * nxv, n2.z * nxv, n2.w * nxv,
                           n3.x * nxv, n3.y * nxv, n3.z * nxv, n3.w * nxv};
            float rs[16];
            #pragma unroll
            for (int e = 0; e < 16; ++e)
                rs[e] = v[e] - __bfloat162float(__float2bfloat16(v[e]));
            unsigned char* ah = smem + OFF_A + (bc ^ 1) * ABUF + (((0 * 8 + gslab) * 4 + q) * 32) * 16;
            unsigned char* al = smem + OFF_A + (bc ^ 1) * ABUF + (((1 * 8 + gslab) * 4 + q) * 32) * 16;
            #pragma unroll
            for (int p = 0; p < 4; ++p) {
                *(uint2*)(ah + (glane4 + p) * 16 + gregoff) =
                    make_uint2(packbf(v[2 * p], v[2 * p + 1]), packbf(v[8 + 2 * p], v[9 + 2 * p]));
                *(uint2*)(al + (glane4 + p) * 16 + gregoff) =
                    make_uint2(packbf(rs[2 * p], rs[2 * p + 1]), packbf(rs[8 + 2 * p], rs[9 + 2 * p]));
            }
        }
        __syncthreads();
    }

    // ---- epilogue: write fo/s pieces, stage MLP weights ----
    float* sFO = (float*)(smem + EXP_FO);
    float* sS  = (float*)(smem + EXP_S);
    float* sM  = (float*)(smem + EXP_M);
    float* sH  = (float*)(smem + EXP_H);

    {
        const int r0 = slab * 16 + (l >> 2);
        const int r1 = r0 + 8;
        float* dst = nh ? sS : sFO;
        #pragma unroll
        for (int t4 = 0; t4 < 4; ++t4) {
            const int c0 = t4 * 8 + (l & 3) * 2;
            dst[r0 * 33 + c0]     = acc[t4][0];
            dst[r0 * 33 + c0 + 1] = acc[t4][1];
            dst[r1 * 33 + c0]     = acc[t4][2];
            dst[r1 * 33 + c0 + 1] = acc[t4][3];
        }
    }
    for (int i = tid; i < 1024; i += THREADS) {
        sM[i]        = lin1_w[i];
        sM[1056 + i] = lin2_w[i];
    }
    if (tid < 32) {
        sM[1024 + tid] = lin1_b[tid];
        sM[2080 + tid] = lin2_b[tid];
        sM[2112 + tid] = last_w[tid];
    }
    if (tid == 0) sM[2144] = last_b[0];
    __syncthreads();

    // ---- MLP: 4 threads per row, 8 outputs each ----
    const int row = grow;

    float xr[32];
    #pragma unroll
    for (int j = 0; j < 32; ++j) {
        float s = sS[row * 33 + j];
        xr[j] = fmaf(s, s, sFO[row * 33 + j]);
    }
    #pragma unroll
    for (int i = 0; i < 8; ++i) {
        int oi = q * 8 + i;
        float t = sM[1024 + oi];
        #pragma unroll
        for (int j4 = 0; j4 < 8; ++j4) {
            float4 w = *(const float4*)&sM[oi * 32 + j4 * 4];
            t = fmaf(xr[j4 * 4],     w.x, t);
            t = fmaf(xr[j4 * 4 + 1], w.y, t);
            t = fmaf(xr[j4 * 4 + 2], w.z, t);
            t = fmaf(xr[j4 * 4 + 3], w.w, t);
        }
        sH[row * 33 + oi] = fmaxf(t, 0.f);
    }
    __syncthreads();

    float hr[32];
    #pragma unroll
    for (int j = 0; j < 32; ++j) hr[j] = sH[row * 33 + j];
    #pragma unroll
    for (int i = 0; i < 8; ++i) {
        int oi = q * 8 + i;
        float t = sM[2080 + oi];
        #pragma unroll
        for (int j4 = 0; j4 < 8; ++j4) {
            float4 w = *(const float4*)&sM[1056 + oi * 32 + j4 * 4];
            t = fmaf(hr[j4 * 4],     w.x, t);
            t = fmaf(hr[j4 * 4 + 1], w.y, t);
            t = fmaf(hr[j4 * 4 + 2], w.z, t);
            t = fmaf(hr[j4 * 4 + 3], w.w, t);
        }
        sFO[row * 33 + oi] = fmaxf(t, 0.f);   // reuse sFO for h2
    }
    __syncthreads();

    if (q == 0) {
        float o = sM[2144];
        #pragma unroll
        for (int j = 0; j < 32; ++j) o = fmaf(sFO[row * 33 + j], sM[2112 + j], o);
        out[b0 + row] = o;
    }
}

extern "C" void kernel_launch(void* const* d_in, const int* in_sizes, int n_in,
                              void* d_out, int out_size) {
    const int*   Xi     = (const int*)  d_in[0];
    const float* Xv     = (const float*)d_in[1];
    const float* tables = (const float*)d_in[2];
    const float* W1     = (const float*)d_in[3];
    const float* Wi     = (const float*)d_in[4];
    const float* lin1_w = (const float*)d_in[5];
    const float* lin1_b = (const float*)d_in[6];
    const float* lin2_w = (const float*)d_in[7];
    const float* lin2_b = (const float*)d_in[8];
    const float* last_w = (const float*)d_in[9];
    const float* last_b = (const float*)d_in[10];
    float* out = (float*)d_out;

    static bool attr_set = false;
    if (!attr_set) {
        cudaFuncSetAttribute(pnn_kernel, cudaFuncAttributeMaxDynamicSharedMemorySize, SMEM_BYTES);
        attr_set = true;
    }

    prep_kernel<<<(2 * 40 * 8 * 32 * 2 + 255) / 256, 256>>>(W1, Wi);
    pnn_kernel<<<BATCH / ROWSPB, THREADS, SMEM_BYTES>>>(
        Xi, Xv, tables, lin1_w, lin1_b, lin2_w, lin2_b, last_w, last_b, out);
}

// round 7
// speedup vs baseline: 1.6937x; 1.6937x over previous
#include <cuda_runtime.h>
#include <cuda_bf16.h>
#include <cstdint>

#define NFIELD 39
#define VOCAB  200000
#define BATCH  16384
#define ROWSPB 128
#define THREADS 256
#define NCHUNK 10          // 10 chunks x 4 fields (kstep16) = 640 padded k

// B fragments packed for LDS.128: [hl2][kstep40][tpair4][lane32][4xu32]
// regs: t=2tp   -> b0,b1 ; t=2tp+1 -> b0,b1
__device__ __align__(16) uint32_t BfragG[2 * 40 * 4 * 32 * 4];

__global__ void prep_kernel(const float* __restrict__ W1, const float* __restrict__ Wi) {
    int i = blockIdx.x * blockDim.x + threadIdx.x;
    if (i >= 2 * 40 * 4 * 32 * 4) return;
    int reg = i & 3;
    int l   = (i >> 2) & 31;
    int tp  = (i >> 7) & 3;
    int s   = (i >> 9) % 40;
    int hl  = (i >> 9) / 40;
    int t  = tp * 2 + (reg >> 1);
    int n  = t * 8 + (l >> 2);
    int k0 = s * 16 + (l & 3) * 2 + (reg & 1) * 8;
    float v0 = 0.f, v1 = 0.f;
    if (k0 < 624)     v0 = (n < 32) ? W1[n * 624 + k0]     : Wi[(n - 32) * 624 + k0];
    if (k0 + 1 < 624) v1 = (n < 32) ? W1[n * 624 + k0 + 1] : Wi[(n - 32) * 624 + k0 + 1];
    float h0 = __bfloat162float(__float2bfloat16(v0));
    float h1 = __bfloat162float(__float2bfloat16(v1));
    uint32_t w;
    if (hl == 0) {
        asm("cvt.rn.bf16x2.f32 %0, %1, %2;" : "=r"(w) : "f"(h1), "f"(h0));
    } else {
        float r0 = v0 - h0, r1 = v1 - h1;
        asm("cvt.rn.bf16x2.f32 %0, %1, %2;" : "=r"(w) : "f"(r1), "f"(r0));
    }
    BfragG[i] = w;
}

__device__ __forceinline__ uint32_t packbf(float lo_elem, float hi_elem) {
    uint32_t r;
    asm("cvt.rn.bf16x2.f32 %0, %1, %2;" : "=r"(r) : "f"(hi_elem), "f"(lo_elem));
    return r;
}
__device__ __forceinline__ void mma16816(float* d, uint32_t a0, uint32_t a1, uint32_t a2, uint32_t a3,
                                         uint32_t b0, uint32_t b1) {
    asm volatile("mma.sync.aligned.m16n8k16.row.col.f32.bf16.bf16.f32 "
                 "{%0,%1,%2,%3}, {%4,%5,%6,%7}, {%8,%9}, {%0,%1,%2,%3};"
                 : "+f"(d[0]), "+f"(d[1]), "+f"(d[2]), "+f"(d[3])
                 : "r"(a0), "r"(a1), "r"(a2), "r"(a3), "r"(b0), "r"(b1));
}
__device__ __forceinline__ void ldsm4(uint32_t& r0, uint32_t& r1, uint32_t& r2, uint32_t& r3,
                                      uint32_t addr) {
    asm volatile("ldmatrix.sync.aligned.m8n8.x4.shared.b16 {%0,%1,%2,%3}, [%4];"
                 : "=r"(r0), "=r"(r1), "=r"(r2), "=r"(r3) : "r"(addr));
}

// smem layout (bytes):
//   A: 2 bufs x [hl2][slab8][ks4][ (h-half)2 x (row)16 x 16B = 512B ] = 2 x 32768 @ 0
//   B: [hl2][gs40][tp4][lane32][16B] = 163840 @ 65536
#define OFF_A 0
#define ABUF  32768
#define OFF_B 65536
#define SMEM_BYTES (65536 + 163840)
// epilogue aliases inside the A region (65536 B):
#define EXP_FO 0
#define EXP_S  16896
#define EXP_M  33792
#define EXP_H  42384

__global__ __launch_bounds__(THREADS, 1)
void pnn_kernel(const int*   __restrict__ Xi,
                const float* __restrict__ Xv,
                const float* __restrict__ tables,
                const float* __restrict__ lin1_w,
                const float* __restrict__ lin1_b,
                const float* __restrict__ lin2_w,
                const float* __restrict__ lin2_b,
                const float* __restrict__ last_w,
                const float* __restrict__ last_b,
                float*       __restrict__ out) {
    extern __shared__ unsigned char smem[];
    const uint32_t sbase = (uint32_t)__cvta_generic_to_shared(smem);

    const int tid = threadIdx.x;
    const int wid = tid >> 5;
    const int l   = tid & 31;
    const int b0  = blockIdx.x * ROWSPB;
    const int slab = wid;            // warp owns rows [slab*16, slab*16+16), all 8 ntiles

    // gather mapping: quad per (row, round): 4 threads x 16B segments of one 64B row
    const int growq = tid >> 2;      // 0..63 ; round r adds 64
    const int q     = tid & 3;       // 16B segment

    // pipeline register stages
    int   nidx[3][8];
    float nxv[3][8];
    float4 tdat[2][8];

    float acc[8][4];
    #pragma unroll
    for (int t = 0; t < 8; ++t)
        #pragma unroll
        for (int r = 0; r < 4; ++r) acc[t][r] = 0.f;

    // ---- lambdas ----
    auto load_idx = [&](int c, int slot) {
        #pragma unroll
        for (int it = 0; it < 8; ++it) {
            int r = it >> 2, j = it & 3;
            int f = c * 4 + j;
            int row = r * 64 + growq;
            if (f < NFIELD) {
                nidx[slot][it] = Xi[(size_t)(b0 + row) * NFIELD + f];
                nxv[slot][it]  = Xv[(size_t)(b0 + row) * NFIELD + f];
            } else {
                nidx[slot][it] = 0;
                nxv[slot][it]  = 0.f;
            }
        }
    };
    auto table_ldg = [&](int c) {
        const int islot = c % 3, tslot = c & 1;
        #pragma unroll
        for (int it = 0; it < 8; ++it) {
            int j = it & 3;
            int f = c * 4 + j;
            if (f < NFIELD) {
                tdat[tslot][it] = *((const float4*)(tables + ((long)f * VOCAB + nidx[islot][it]) * 16) + q);
            } else {
                tdat[tslot][it] = make_float4(0.f, 0.f, 0.f, 0.f);
            }
        }
    };
    auto cv_store = [&](int c) {
        const int islot = c % 3, tslot = c & 1;
        #pragma unroll
        for (int it = 0; it < 8; ++it) {
            int r = it >> 2, j = it & 3;
            int row = r * 64 + growq;
            float xv = nxv[islot][it];
            float4 t4 = tdat[tslot][it];
            float v0 = t4.x * xv, v1 = t4.y * xv, v2 = t4.z * xv, v3 = t4.w * xv;
            float r0 = v0 - __bfloat162float(__float2bfloat16(v0));
            float r1 = v1 - __bfloat162float(__float2bfloat16(v1));
            float r2 = v2 - __bfloat162float(__float2bfloat16(v2));
            float r3 = v3 - __bfloat162float(__float2bfloat16(v3));
            int sl = row >> 4;
            int inoff = (q >> 1) * 256 + (row & 15) * 16 + (q & 1) * 8;
            unsigned char* bh = smem + (c & 1) * ABUF + ((0 * 8 + sl) * 4 + j) * 512 + inoff;
            unsigned char* bl = smem + (c & 1) * ABUF + ((1 * 8 + sl) * 4 + j) * 512 + inoff;
            *(uint2*)bh = make_uint2(packbf(v0, v1), packbf(v2, v3));
            *(uint2*)bl = make_uint2(packbf(r0, r1), packbf(r2, r3));
        }
    };
    auto do_mma = [&](int c) {
        #pragma unroll
        for (int s = 0; s < 4; ++s) {
            const int gs = c * 4 + s;
            uint32_t ah0, ah1, ah2, ah3, al0, al1, al2, al3;
            uint32_t laddr = (uint32_t)((l & 15) * 16 + (l >> 4) * 256);
            ldsm4(ah0, ah1, ah2, ah3,
                  sbase + (c & 1) * ABUF + ((0 * 8 + slab) * 4 + s) * 512 + laddr);
            ldsm4(al0, al1, al2, al3,
                  sbase + (c & 1) * ABUF + ((1 * 8 + slab) * 4 + s) * 512 + laddr);
            #pragma unroll
            for (int tp = 0; tp < 4; ++tp) {
                uint4 Bh = *(const uint4*)(smem + OFF_B + (((0 * 40 + gs) * 4 + tp) * 32 + l) * 16);
                uint4 Bl = *(const uint4*)(smem + OFF_B + (((1 * 40 + gs) * 4 + tp) * 32 + l) * 16);
                mma16816(acc[2 * tp],     ah0, ah1, ah2, ah3, Bh.x, Bh.y);
                mma16816(acc[2 * tp + 1], ah0, ah1, ah2, ah3, Bh.z, Bh.w);
                mma16816(acc[2 * tp],     ah0, ah1, ah2, ah3, Bl.x, Bl.y);
                mma16816(acc[2 * tp + 1], ah0, ah1, ah2, ah3, Bl.z, Bl.w);
                mma16816(acc[2 * tp],     al0, al1, al2, al3, Bh.x, Bh.y);
                mma16816(acc[2 * tp + 1], al0, al1, al2, al3, Bh.z, Bh.w);
            }
        }
    };

    // ---- prologue ----
    load_idx(0, 0);
    load_idx(1, 1);
    load_idx(2, 2);
    // stage B fragments (160KB) while idx loads fly
    {
        const uint4* src = (const uint4*)BfragG;
        uint4* dst = (uint4*)(smem + OFF_B);
        #pragma unroll 4
        for (int i = tid; i < 163840 / 16; i += THREADS) dst[i] = src[i];
    }
    table_ldg(0);
    table_ldg(1);
    cv_store(0);
    __syncthreads();

    // ---- fully-unrolled pipelined main loop ----
    #pragma unroll
    for (int c = 0; c < NCHUNK; ++c) {
        if (c + 3 < NCHUNK) load_idx(c + 3, (c + 3) % 3);
        if (c + 2 < NCHUNK) table_ldg(c + 2);
        do_mma(c);
        if (c + 1 < NCHUNK) cv_store(c + 1);
        __syncthreads();
    }

    // ---- epilogue ----
    float* sFO = (float*)(smem + EXP_FO);
    float* sS  = (float*)(smem + EXP_S);
    float* sM  = (float*)(smem + EXP_M);
    float* sH  = (float*)(smem + EXP_H);

    {
        const int r0 = slab * 16 + (l >> 2);
        const int r1 = r0 + 8;
        #pragma unroll
        for (int t = 0; t < 4; ++t) {
            const int c0 = t * 8 + (l & 3) * 2;
            sFO[r0 * 33 + c0]     = acc[t][0];
            sFO[r0 * 33 + c0 + 1] = acc[t][1];
            sFO[r1 * 33 + c0]     = acc[t][2];
            sFO[r1 * 33 + c0 + 1] = acc[t][3];
            sS[r0 * 33 + c0]      = acc[t + 4][0];
            sS[r0 * 33 + c0 + 1]  = acc[t + 4][1];
            sS[r1 * 33 + c0]      = acc[t + 4][2];
            sS[r1 * 33 + c0 + 1]  = acc[t + 4][3];
        }
    }
    for (int i = tid; i < 1024; i += THREADS) {
        sM[i]        = lin1_w[i];
        sM[1056 + i] = lin2_w[i];
    }
    if (tid < 32) {
        sM[1024 + tid] = lin1_b[tid];
        sM[2080 + tid] = lin2_b[tid];
        sM[2112 + tid] = last_w[tid];
    }
    if (tid == 0) sM[2144] = last_b[0];
    __syncthreads();

    // ---- MLP: 2 threads per row, 16 outputs each ----
    const int mrow = tid >> 1;
    const int mh   = tid & 1;

    float xr[32];
    #pragma unroll
    for (int j = 0; j < 32; ++j) {
        float s = sS[mrow * 33 + j];
        xr[j] = fmaf(s, s, sFO[mrow * 33 + j]);
    }
    #pragma unroll
    for (int i = 0; i < 16; ++i) {
        int oi = mh * 16 + i;
        float t = sM[1024 + oi];
        #pragma unroll
        for (int j4 = 0; j4 < 8; ++j4) {
            float4 w = *(const float4*)&sM[oi * 32 + j4 * 4];
            t = fmaf(xr[j4 * 4],     w.x, t);
            t = fmaf(xr[j4 * 4 + 1], w.y, t);
            t = fmaf(xr[j4 * 4 + 2], w.z, t);
            t = fmaf(xr[j4 * 4 + 3], w.w, t);
        }
        sH[mrow * 33 + oi] = fmaxf(t, 0.f);
    }
    __syncthreads();

    float hr[32];
    #pragma unroll
    for (int j = 0; j < 32; ++j) hr[j] = sH[mrow * 33 + j];
    #pragma unroll
    for (int i = 0; i < 16; ++i) {
        int oi = mh * 16 + i;
        float t = sM[2080 + oi];
        #pragma unroll
        for (int j4 = 0; j4 < 8; ++j4) {
            float4 w = *(const float4*)&sM[1056 + oi * 32 + j4 * 4];
            t = fmaf(hr[j4 * 4],     w.x, t);
            t = fmaf(hr[j4 * 4 + 1], w.y, t);
            t = fmaf(hr[j4 * 4 + 2], w.z, t);
            t = fmaf(hr[j4 * 4 + 3], w.w, t);
        }
        sFO[mrow * 33 + oi] = fmaxf(t, 0.f);   // reuse sFO for h2
    }
    __syncthreads();

    if (mh == 0) {
        float o = sM[2144];
        #pragma unroll
        for (int j = 0; j < 32; ++j) o = fmaf(sFO[mrow * 33 + j], sM[2112 + j], o);
        out[b0 + mrow] = o;
    }
}

extern "C" void kernel_launch(void* const* d_in, const int* in_sizes, int n_in,
                              void* d_out, int out_size) {
    const int*   Xi     = (const int*)  d_in[0];
    const float* Xv     = (const float*)d_in[1];
    const float* tables = (const float*)d_in[2];
    const float* W1     = (const float*)d_in[3];
    const float* Wi     = (const float*)d_in[4];
    const float* lin1_w = (const float*)d_in[5];
    const float* lin1_b = (const float*)d_in[6];
    const float* lin2_w = (const float*)d_in[7];
    const float* lin2_b = (const float*)d_in[8];
    const float* last_w = (const float*)d_in[9];
    const float* last_b = (const float*)d_in[10];
    float* out = (float*)d_out;

    static bool attr_set = false;
    if (!attr_set) {
        cudaFuncSetAttribute(pnn_kernel, cudaFuncAttributeMaxDynamicSharedMemorySize, SMEM_BYTES);
        attr_set = true;
    }

    prep_kernel<<<(2 * 40 * 4 * 32 * 4 + 255) / 256, 256>>>(W1, Wi);
    pnn_kernel<<<BATCH / ROWSPB, THREADS, SMEM_BYTES>>>(
        Xi, Xv, tables, lin1_w, lin1_b, lin2_w, lin2_b, last_w, last_b, out);
}